// round 9
// baseline (speedup 1.0000x reference)
#include <cuda_runtime.h>

// ---------------------------------------------------------------------------
// GraphConstruction: A[i,j] = all_k( ||patch_i[:,k]-patch_j[:,k]||_2 <= 7 )
// score_k(i,j) = sum_{r<16} P[i,r,k]*P[j,r,k] + 1*c_j + c_i*1,  c = 12.25-sq/2
// A[i,j] = no k has score_k < 0 (OR of sign bits == 0).
// gram kernel: identical to R6/R7 (pipe-floor bound, bit-stable rel_err).
// R8: prep1 rebuilt as smem-transpose copy (LDG.128 full sectors -> STG.128).
// ---------------------------------------------------------------------------

#define NP 4096
#define RAUG 18

static __device__ float g_P[16 * RAUG * NP];   // [k][r][n], 4.5 MB

// ---------------- helpers ---------------------------------------------------
__device__ __forceinline__ unsigned long long bcast2(float x) {
    unsigned long long r;
    asm("mov.b64 %0, {%1, %1};" : "=l"(r) : "f"(x));
    return r;
}
__device__ __forceinline__ void ffma2(unsigned long long& d,
                                      unsigned long long a,
                                      unsigned long long b) {
    asm("fma.rn.f32x2 %0, %1, %2, %3;" : "=l"(d) : "l"(a), "l"(b), "l"(d));
}
__device__ __forceinline__ void split2(unsigned& lo, unsigned& hi,
                                       unsigned long long v) {
    asm("mov.b64 {%0, %1}, %2;" : "=r"(lo), "=r"(hi) : "l"(v));
}
__device__ __forceinline__ unsigned prmt(unsigned a, unsigned b, unsigned sel) {
    unsigned d;
    asm("prmt.b32 %0, %1, %2, %3;" : "=r"(d) : "r"(a), "r"(b), "r"(sel));
    return d;
}
__device__ __forceinline__ void cp_async16(void* smem, const void* gmem) {
    unsigned s = (unsigned)__cvta_generic_to_shared(smem);
    asm volatile("cp.async.cg.shared.global [%0], [%1], 16;" :: "r"(s), "l"(gmem));
}
#define CP_COMMIT() asm volatile("cp.async.commit_group;")
#define CP_WAIT0()  asm volatile("cp.async.wait_group 0;")

// ---------------- prep 1: gather x into g_P rows 0..15 ----------------------
// Block = (r, k, half-of-m). Thread (c = n&15, mm = local n>>8) loads the 16
// j-values (64B contiguous in x, full sectors), transposes via smem, writes
// 16 consecutive n as 4x STG.128. Values bit-identical to prior rounds.
__global__ void __launch_bounds__(128) prep1_kernel(const float* __restrict__ x) {
    __shared__ float sm[2080];                 // 2048 + 4-pad per 256
    const int b = blockIdx.x;                  // 512 blocks: r*32 + k*2 + half
    const int half = b & 1;
    const int k = (b >> 1) & 15;
    const int r = b >> 5;
    const int t = threadIdx.x;                 // 128 threads
    const int c = t & 15;                      // n & 15
    const int mm = t >> 4;                     // local (n>>8): 0..7
    const int m = half * 8 + mm;
    const int h = c * 64 + ((r >> 2) << 4) + m;
    const int wb = (16 * (r & 3) + k) << 4;

    const float* src = &x[h * 1024 + wb];      // 16 j values, 64B contiguous
    float4 L0 = *(const float4*)(src);
    float4 L1 = *(const float4*)(src + 4);
    float4 L2 = *(const float4*)(src + 8);
    float4 L3 = *(const float4*)(src + 12);

    // n_local = c + 16*j + 256*mm ; smem addr = n_local + 4*(n_local>>8)
    const int base = c + 260 * mm;
    sm[base +   0] = L0.x; sm[base +  16] = L0.y;
    sm[base +  32] = L0.z; sm[base +  48] = L0.w;
    sm[base +  64] = L1.x; sm[base +  80] = L1.y;
    sm[base +  96] = L1.z; sm[base + 112] = L1.w;
    sm[base + 128] = L2.x; sm[base + 144] = L2.y;
    sm[base + 160] = L2.z; sm[base + 176] = L2.w;
    sm[base + 192] = L3.x; sm[base + 208] = L3.y;
    sm[base + 224] = L3.z; sm[base + 240] = L3.w;
    __syncthreads();

    // read 16 consecutive n_local = t*16.. ; padded addr stays contiguous
    float* dst = &g_P[(k * RAUG + r) * NP + half * 2048 + t * 16];
    const int ra = t * 16 + 4 * (t >> 4);
    *(float4*)(dst)      = *(const float4*)&sm[ra];
    *(float4*)(dst + 4)  = *(const float4*)&sm[ra + 4];
    *(float4*)(dst + 8)  = *(const float4*)&sm[ra + 8];
    *(float4*)(dst + 12) = *(const float4*)&sm[ra + 12];
}

// ---------------- prep 2: augmentation rows 16,17 ---------------------------
// 2 n per thread (float2); per-n scalar fmaf chain r=0..15 (bit-identical sq).
__global__ void prep2_kernel() {
    int idx = blockIdx.x * blockDim.x + threadIdx.x;   // [0, 16*2048)
    int n2 = idx & 2047;
    int k = idx >> 11;
    float s0 = 0.0f, s1 = 0.0f;
#pragma unroll
    for (int r = 0; r < 16; r++) {
        float2 v = *(const float2*)&g_P[(k * RAUG + r) * NP + n2 * 2];
        s0 = fmaf(v.x, v.x, s0);
        s1 = fmaf(v.y, v.y, s1);
    }
    *(float2*)&g_P[(k * RAUG + 16) * NP + n2 * 2] = make_float2(1.0f, 1.0f);
    *(float2*)&g_P[(k * RAUG + 17) * NP + n2 * 2] =
        make_float2(12.25f - 0.5f * s0, 12.25f - 0.5f * s1);
}

// ---------------- main: tiled pair kernel (identical to R6/R7) --------------
// Tile 64 i x 64 j, 64 threads, 8x8 per thread (j packed as f32x2).
__global__ void __launch_bounds__(64, 8) gram_kernel(float* __restrict__ A) {
    const int bid = blockIdx.x;
    int jb = (int)((sqrtf(8.0f * (float)bid + 1.0f) - 1.0f) * 0.5f);
    while ((jb * (jb + 1)) / 2 > bid) jb--;
    while (((jb + 1) * (jb + 2)) / 2 <= bid) jb++;
    const int ib = bid - (jb * (jb + 1)) / 2;   // 0..jb
    const int i0 = ib * 64;
    const int j0 = jb * 64;

    __shared__ __align__(16) float sA[2][RAUG][64];
    __shared__ __align__(16) float sB[2][RAUG][64];

    const int tid = threadIdx.x;
    const int tx = tid & 7;              // j group: j = {tx*4..+3} U {32+tx*4..+3}
    const int ty = tid >> 3;             // i group 0..7

    auto issue = [&](int buf, int k) {
        for (int idx = tid; idx < 288; idx += 64) {      // sA: 18 x 16 float4
            int r = idx >> 4, c = idx & 15;
            cp_async16(&sA[buf][r][c * 4], &g_P[(k * RAUG + r) * NP + i0 + c * 4]);
        }
        for (int idx = tid; idx < 288; idx += 64) {      // sB: rows 16/17 swapped
            int r = idx >> 4, c = idx & 15;
            int rs = (r < 16) ? r : (33 - r);
            cp_async16(&sB[buf][r][c * 4], &g_P[(k * RAUG + rs) * NP + j0 + c * 4]);
        }
    };

    unsigned msk[8][2];
#pragma unroll
    for (int a = 0; a < 8; a++) { msk[a][0] = 0u; msk[a][1] = 0u; }

    issue(0, 0);
    CP_COMMIT();

#pragma unroll 1
    for (int k = 0; k < 16; k++) {
        const int buf = k & 1;
        CP_WAIT0();
        __syncthreads();          // buf staged AND everyone done with buf^1
        if (k < 15) {
            issue(buf ^ 1, k + 1);
            CP_COMMIT();
        }

        unsigned long long acc[8][4];
#pragma unroll
        for (int a = 0; a < 8; a++)
#pragma unroll
            for (int b = 0; b < 4; b++) acc[a][b] = 0ULL;

#pragma unroll
        for (int r = 0; r < RAUG; r++) {
            float4 a0 = *(const float4*)&sA[buf][r][ty * 8];
            float4 a1 = *(const float4*)&sA[buf][r][ty * 8 + 4];
            ulonglong2 b0 = *(const ulonglong2*)&sB[buf][r][tx * 4];
            ulonglong2 b1 = *(const ulonglong2*)&sB[buf][r][32 + tx * 4];
            unsigned long long bb[4] = {b0.x, b0.y, b1.x, b1.y};
            float av[8] = {a0.x, a0.y, a0.z, a0.w, a1.x, a1.y, a1.z, a1.w};
#pragma unroll
            for (int ii = 0; ii < 8; ii++) {
                unsigned long long aa = bcast2(av[ii]);
#pragma unroll
                for (int jj = 0; jj < 4; jj++) ffma2(acc[ii][jj], aa, bb[jj]);
            }
        }

        // fold sign bits: msk[ii][p] bytes = signs of j = p*32 + tx*4 + {0..3}
#pragma unroll
        for (int ii = 0; ii < 8; ii++)
#pragma unroll
            for (int p = 0; p < 2; p++) {
                unsigned lo0, hi0, lo1, hi1;
                split2(lo0, hi0, acc[ii][2 * p]);
                split2(lo1, hi1, acc[ii][2 * p + 1]);
                unsigned t0 = prmt(lo0, hi0, 0xFBFBu);
                unsigned t1 = prmt(lo1, hi1, 0xFBFBu);
                msk[ii][p] |= prmt(t0, t1, 0x5410u);
            }
    }

    // ---- epilogue: sign byte==0 -> 1.0f ----
    // direct: A[i, j]
#pragma unroll
    for (int ii = 0; ii < 8; ii++)
#pragma unroll
        for (int p = 0; p < 2; p++) {
            unsigned m = msk[ii][p];
            float4 o;
            o.x = (m & 0x00000080u) ? 0.0f : 1.0f;
            o.y = (m & 0x00008000u) ? 0.0f : 1.0f;
            o.z = (m & 0x00800000u) ? 0.0f : 1.0f;
            o.w = (m & 0x80000000u) ? 0.0f : 1.0f;
            size_t off = (size_t)(i0 + ty * 8 + ii) * 4096 + j0 + p * 32 + tx * 4;
            *(float4*)&A[off] = o;
        }
    // transposed: A[j, i]; skip rows inside this tile's i-range (diag tiles)
#pragma unroll
    for (int p = 0; p < 2; p++)
#pragma unroll
        for (int c = 0; c < 4; c++) {
            int rowj = j0 + p * 32 + tx * 4 + c;
            if (rowj >= i0 && rowj < i0 + 64) continue;   // diag: direct covers
            unsigned bit = 0x80u << (8 * c);
            float4 o0, o1;
            o0.x = (msk[0][p] & bit) ? 0.0f : 1.0f;
            o0.y = (msk[1][p] & bit) ? 0.0f : 1.0f;
            o0.z = (msk[2][p] & bit) ? 0.0f : 1.0f;
            o0.w = (msk[3][p] & bit) ? 0.0f : 1.0f;
            o1.x = (msk[4][p] & bit) ? 0.0f : 1.0f;
            o1.y = (msk[5][p] & bit) ? 0.0f : 1.0f;
            o1.z = (msk[6][p] & bit) ? 0.0f : 1.0f;
            o1.w = (msk[7][p] & bit) ? 0.0f : 1.0f;
            size_t off = (size_t)rowj * 4096 + i0 + ty * 8;
            *(float4*)&A[off]     = o0;
            *(float4*)&A[off + 4] = o1;
        }
}

// ---------------------------------------------------------------------------
extern "C" void kernel_launch(void* const* d_in, const int* in_sizes, int n_in,
                              void* d_out, int out_size) {
    const float* x = (const float*)d_in[0];
    float* A = (float*)d_out;

    prep1_kernel<<<512, 128>>>(x);         // smem-transpose gather
    prep2_kernel<<<128, 256>>>();          // rows 16,17 (2 n / thread)
    gram_kernel<<<2080, 64>>>(A);          // 64x64 triangle tiles
}

// round 10
// speedup vs baseline: 1.0249x; 1.0249x over previous
#include <cuda_runtime.h>

// ---------------------------------------------------------------------------
// GraphConstruction: A[i,j] = all_k( ||patch_i[:,k]-patch_j[:,k]||_2 <= 7 )
// score_k(i,j) = sum_{r<16} P[i,r,k]*P[j,r,k] + 1*c_j + c_i*1,  c = 12.25-sq/2
// A[i,j] = no k has score_k < 0 (OR of sign bits == 0).
// gram kernel: identical to R6/R7 (pipe-floor bound, bit-stable rel_err).
// R9: prep1+prep2 fused into one pass (v[] kept in registers for sq chain).
// ---------------------------------------------------------------------------

#define NP 4096
#define RAUG 18

static __device__ float g_P[16 * RAUG * NP];   // [k][r][n], 4.5 MB

// ---------------- helpers ---------------------------------------------------
__device__ __forceinline__ unsigned long long bcast2(float x) {
    unsigned long long r;
    asm("mov.b64 %0, {%1, %1};" : "=l"(r) : "f"(x));
    return r;
}
__device__ __forceinline__ void ffma2(unsigned long long& d,
                                      unsigned long long a,
                                      unsigned long long b) {
    asm("fma.rn.f32x2 %0, %1, %2, %3;" : "=l"(d) : "l"(a), "l"(b), "l"(d));
}
__device__ __forceinline__ void split2(unsigned& lo, unsigned& hi,
                                       unsigned long long v) {
    asm("mov.b64 {%0, %1}, %2;" : "=r"(lo), "=r"(hi) : "l"(v));
}
__device__ __forceinline__ unsigned prmt(unsigned a, unsigned b, unsigned sel) {
    unsigned d;
    asm("prmt.b32 %0, %1, %2, %3;" : "=r"(d) : "r"(a), "r"(b), "r"(sel));
    return d;
}
__device__ __forceinline__ void cp_async16(void* smem, const void* gmem) {
    unsigned s = (unsigned)__cvta_generic_to_shared(smem);
    asm volatile("cp.async.cg.shared.global [%0], [%1], 16;" :: "r"(s), "l"(gmem));
}
#define CP_COMMIT() asm volatile("cp.async.commit_group;")
#define CP_WAIT0()  asm volatile("cp.async.wait_group 0;")

// ---------------- fused prep: gather + augmentation --------------------------
// Block = (k, quarter q). Thread owns one n: loads all 16 r values (MLP=16),
// writes rows 0..15 (coalesced across lanes), computes sq from registers via
// the same ascending-r fmaf chain as before (bit-identical), writes rows 16/17.
__global__ void __launch_bounds__(256) prep_kernel(const float* __restrict__ x) {
    const int k = blockIdx.x >> 4;
    const int q = blockIdx.x & 15;
    const int t = threadIdx.x;                 // 256 threads
    const int n = q * 256 + t;
    const int c = n & 15;
    const int j = (n >> 4) & 15;
    const int m = n >> 8;

    float v[16];
#pragma unroll
    for (int r = 0; r < 16; r++) {
        int h = (c << 6) + ((r >> 2) << 4) + m;
        int w = ((16 * (r & 3) + k) << 4) + j;
        v[r] = x[h * 1024 + w];
    }
#pragma unroll
    for (int r = 0; r < 16; r++)
        g_P[(k * RAUG + r) * NP + n] = v[r];

    float s = 0.0f;
#pragma unroll
    for (int r = 0; r < 16; r++)
        s = fmaf(v[r], v[r], s);               // identical chain to prep2

    g_P[(k * RAUG + 16) * NP + n] = 1.0f;
    g_P[(k * RAUG + 17) * NP + n] = 12.25f - 0.5f * s;
}

// ---------------- main: tiled pair kernel (identical to R6/R7) --------------
// Tile 64 i x 64 j, 64 threads, 8x8 per thread (j packed as f32x2).
__global__ void __launch_bounds__(64, 8) gram_kernel(float* __restrict__ A) {
    const int bid = blockIdx.x;
    int jb = (int)((sqrtf(8.0f * (float)bid + 1.0f) - 1.0f) * 0.5f);
    while ((jb * (jb + 1)) / 2 > bid) jb--;
    while (((jb + 1) * (jb + 2)) / 2 <= bid) jb++;
    const int ib = bid - (jb * (jb + 1)) / 2;   // 0..jb
    const int i0 = ib * 64;
    const int j0 = jb * 64;

    __shared__ __align__(16) float sA[2][RAUG][64];
    __shared__ __align__(16) float sB[2][RAUG][64];

    const int tid = threadIdx.x;
    const int tx = tid & 7;              // j group: j = {tx*4..+3} U {32+tx*4..+3}
    const int ty = tid >> 3;             // i group 0..7

    auto issue = [&](int buf, int k) {
        for (int idx = tid; idx < 288; idx += 64) {      // sA: 18 x 16 float4
            int r = idx >> 4, c = idx & 15;
            cp_async16(&sA[buf][r][c * 4], &g_P[(k * RAUG + r) * NP + i0 + c * 4]);
        }
        for (int idx = tid; idx < 288; idx += 64) {      // sB: rows 16/17 swapped
            int r = idx >> 4, c = idx & 15;
            int rs = (r < 16) ? r : (33 - r);
            cp_async16(&sB[buf][r][c * 4], &g_P[(k * RAUG + rs) * NP + j0 + c * 4]);
        }
    };

    unsigned msk[8][2];
#pragma unroll
    for (int a = 0; a < 8; a++) { msk[a][0] = 0u; msk[a][1] = 0u; }

    issue(0, 0);
    CP_COMMIT();

#pragma unroll 1
    for (int k = 0; k < 16; k++) {
        const int buf = k & 1;
        CP_WAIT0();
        __syncthreads();          // buf staged AND everyone done with buf^1
        if (k < 15) {
            issue(buf ^ 1, k + 1);
            CP_COMMIT();
        }

        unsigned long long acc[8][4];
#pragma unroll
        for (int a = 0; a < 8; a++)
#pragma unroll
            for (int b = 0; b < 4; b++) acc[a][b] = 0ULL;

#pragma unroll
        for (int r = 0; r < RAUG; r++) {
            float4 a0 = *(const float4*)&sA[buf][r][ty * 8];
            float4 a1 = *(const float4*)&sA[buf][r][ty * 8 + 4];
            ulonglong2 b0 = *(const ulonglong2*)&sB[buf][r][tx * 4];
            ulonglong2 b1 = *(const ulonglong2*)&sB[buf][r][32 + tx * 4];
            unsigned long long bb[4] = {b0.x, b0.y, b1.x, b1.y};
            float av[8] = {a0.x, a0.y, a0.z, a0.w, a1.x, a1.y, a1.z, a1.w};
#pragma unroll
            for (int ii = 0; ii < 8; ii++) {
                unsigned long long aa = bcast2(av[ii]);
#pragma unroll
                for (int jj = 0; jj < 4; jj++) ffma2(acc[ii][jj], aa, bb[jj]);
            }
        }

        // fold sign bits: msk[ii][p] bytes = signs of j = p*32 + tx*4 + {0..3}
#pragma unroll
        for (int ii = 0; ii < 8; ii++)
#pragma unroll
            for (int p = 0; p < 2; p++) {
                unsigned lo0, hi0, lo1, hi1;
                split2(lo0, hi0, acc[ii][2 * p]);
                split2(lo1, hi1, acc[ii][2 * p + 1]);
                unsigned t0 = prmt(lo0, hi0, 0xFBFBu);
                unsigned t1 = prmt(lo1, hi1, 0xFBFBu);
                msk[ii][p] |= prmt(t0, t1, 0x5410u);
            }
    }

    // ---- epilogue: sign byte==0 -> 1.0f ----
    // direct: A[i, j]
#pragma unroll
    for (int ii = 0; ii < 8; ii++)
#pragma unroll
        for (int p = 0; p < 2; p++) {
            unsigned m = msk[ii][p];
            float4 o;
            o.x = (m & 0x00000080u) ? 0.0f : 1.0f;
            o.y = (m & 0x00008000u) ? 0.0f : 1.0f;
            o.z = (m & 0x00800000u) ? 0.0f : 1.0f;
            o.w = (m & 0x80000000u) ? 0.0f : 1.0f;
            size_t off = (size_t)(i0 + ty * 8 + ii) * 4096 + j0 + p * 32 + tx * 4;
            *(float4*)&A[off] = o;
        }
    // transposed: A[j, i]; skip rows inside this tile's i-range (diag tiles)
#pragma unroll
    for (int p = 0; p < 2; p++)
#pragma unroll
        for (int c = 0; c < 4; c++) {
            int rowj = j0 + p * 32 + tx * 4 + c;
            if (rowj >= i0 && rowj < i0 + 64) continue;   // diag: direct covers
            unsigned bit = 0x80u << (8 * c);
            float4 o0, o1;
            o0.x = (msk[0][p] & bit) ? 0.0f : 1.0f;
            o0.y = (msk[1][p] & bit) ? 0.0f : 1.0f;
            o0.z = (msk[2][p] & bit) ? 0.0f : 1.0f;
            o0.w = (msk[3][p] & bit) ? 0.0f : 1.0f;
            o1.x = (msk[4][p] & bit) ? 0.0f : 1.0f;
            o1.y = (msk[5][p] & bit) ? 0.0f : 1.0f;
            o1.z = (msk[6][p] & bit) ? 0.0f : 1.0f;
            o1.w = (msk[7][p] & bit) ? 0.0f : 1.0f;
            size_t off = (size_t)rowj * 4096 + i0 + ty * 8;
            *(float4*)&A[off]     = o0;
            *(float4*)&A[off + 4] = o1;
        }
}

// ---------------------------------------------------------------------------
extern "C" void kernel_launch(void* const* d_in, const int* in_sizes, int n_in,
                              void* d_out, int out_size) {
    const float* x = (const float*)d_in[0];
    float* A = (float*)d_out;

    prep_kernel<<<256, 256>>>(x);          // fused gather + augmentation
    gram_kernel<<<2080, 64>>>(A);          // 64x64 triangle tiles
}